// round 1
// baseline (speedup 1.0000x reference)
#include <cuda_runtime.h>
#include <math.h>

// Model dims
#define BB 8
#define NN 256
#define DD 48
#define VV 20
#define LL 2
#define SS 6
#define TWO_D 96
#define THREE_D 144
#define FOUR_D 192
#define ROWS (BB*NN)   // 2048

// Scratch (no cudaMalloc allowed)
__device__ float g_x[ROWS * DD];
__device__ float g_p[ROWS * DD];
__device__ float g_t[ROWS * DD];

__device__ __forceinline__ float gelu_exact(float v) {
    return 0.5f * v * (1.0f + erff(v * 0.70710678118654752440f));
}

// ---------------------------------------------------------------------------
// Embed: x[b,n,:] = embed[ids[b,n],:] + pos[n,:]
// ---------------------------------------------------------------------------
__global__ void embed_kernel(const int* __restrict__ ids,
                             const float* __restrict__ embed,
                             const float* __restrict__ pos,
                             float* __restrict__ x) {
    int row = blockIdx.x;           // b*N + n
    int n = row & (NN - 1);
    int d = threadIdx.x;            // 48 threads
    int id = ids[row];
    x[row * DD + d] = embed[id * DD + d] + pos[n * DD + d];
}

// ---------------------------------------------------------------------------
// Pair module, fused with masked online softmax.
// One block per (b,i), 8 warps; warp w handles j = w, w+8, ... <= i.
// ---------------------------------------------------------------------------
#define PAIR_WARPS 8
#define PAIR_THREADS (PAIR_WARPS*32)

__global__ __launch_bounds__(PAIR_THREADS) void pair_kernel(
    const float* __restrict__ x,
    const float* __restrict__ W1, const float* __restrict__ B1,
    const float* __restrict__ W2, const float* __restrict__ B2,
    float* __restrict__ outp) {
    extern __shared__ float sh[];
    float* sW1 = sh;                       // 96*96
    float* sW2 = sW1 + TWO_D * TWO_D;      // 96*48
    float* sb1 = sW2 + TWO_D * DD;         // 96
    float* sb2 = sb1 + TWO_D;              // 48
    float* sxi = sb2 + DD;                 // 48
    float* sxj = sxi + DD;                 // 8*48
    float* shh = sxj + PAIR_WARPS * DD;    // 8*96
    float* sred = shh + PAIR_WARPS * TWO_D;// 8*50

    int row = blockIdx.x;
    int b = row >> 8;
    int i = row & (NN - 1);
    int tid = threadIdx.x;

    for (int t = tid; t < TWO_D * TWO_D; t += PAIR_THREADS) sW1[t] = W1[t];
    for (int t = tid; t < TWO_D * DD; t += PAIR_THREADS)    sW2[t] = W2[t];
    if (tid < TWO_D) sb1[tid] = B1[tid];
    if (tid < DD) { sb2[tid] = B2[tid]; sxi[tid] = x[row * DD + tid]; }
    __syncthreads();

    int w = tid >> 5;
    int lane = tid & 31;
    bool hasHi = (lane < 16);

    float m = -INFINITY, lsum = 0.0f, acc0 = 0.0f, acc1 = 0.0f;
    float* hw = shh + w * TWO_D;
    float* xjw = sxj + w * DD;

    for (int j = w; j <= i; j += PAIR_WARPS) {
        const float* xj = x + (b * NN + j) * DD;
        if (lane < 24) { xjw[lane] = xj[lane]; xjw[lane + 24] = xj[lane + 24]; }
        __syncwarp();

        float h0 = sb1[lane], h1 = sb1[lane + 32], h2 = sb1[lane + 64];
        #pragma unroll 6
        for (int c = 0; c < TWO_D; c++) {
            float vc = (c < DD) ? sxi[c] : xjw[c - DD];
            const float* wrow = sW1 + c * TWO_D;
            h0 = fmaf(vc, wrow[lane], h0);
            h1 = fmaf(vc, wrow[lane + 32], h1);
            h2 = fmaf(vc, wrow[lane + 64], h2);
        }
        hw[lane] = gelu_exact(h0);
        hw[lane + 32] = gelu_exact(h1);
        hw[lane + 64] = gelu_exact(h2);
        __syncwarp();

        float p0 = sb2[lane];
        float p1 = hasHi ? sb2[lane + 32] : 0.0f;
        #pragma unroll 6
        for (int k = 0; k < TWO_D; k++) {
            float hk = hw[k];
            p0 = fmaf(hk, sW2[k * DD + lane], p0);
            if (hasHi) p1 = fmaf(hk, sW2[k * DD + lane + 32], p1);
        }
        float sq = p0 * p0 + (hasHi ? p1 * p1 : 0.0f);
        #pragma unroll
        for (int o = 16; o > 0; o >>= 1) sq += __shfl_xor_sync(0xFFFFFFFFu, sq, o);
        float wj = sqrtf(sq);

        float mnew = fmaxf(m, wj);
        float scale = __expf(0.0f) == 1.0f ? expf(m - mnew) : expf(m - mnew); // expf exact path
        float e = expf(wj - mnew);
        lsum = lsum * scale + e;
        acc0 = acc0 * scale + e * p0;
        acc1 = acc1 * scale + e * p1;
        m = mnew;
        __syncwarp();
    }

    float* r = sred + w * 50;
    if (lane == 0) { r[0] = m; r[1] = lsum; }
    r[2 + lane] = acc0;
    if (hasHi) r[2 + 32 + lane] = acc1;
    __syncthreads();

    if (tid < DD) {
        float M = -INFINITY;
        #pragma unroll
        for (int ww = 0; ww < PAIR_WARPS; ww++) M = fmaxf(M, sred[ww * 50]);
        float L = 0.0f, a = 0.0f;
        #pragma unroll
        for (int ww = 0; ww < PAIR_WARPS; ww++) {
            float s = expf(sred[ww * 50] - M);
            L += sred[ww * 50 + 1] * s;
            a += sred[ww * 50 + 2 + tid] * s;
        }
        outp[row * DD + tid] = a / L;
    }
}

// ---------------------------------------------------------------------------
// Triple module: gather j/k, MLP 144->96->48, mean over S.
// One block per (b,i), 96 threads.
// ---------------------------------------------------------------------------
__global__ void triple_kernel(const float* __restrict__ x,
                              const int* __restrict__ ji,
                              const int* __restrict__ ki,
                              const float* __restrict__ W1,
                              const float* __restrict__ B1,
                              const float* __restrict__ W2,
                              const float* __restrict__ B2,
                              float* __restrict__ outt) {
    __shared__ float v[THREE_D];
    __shared__ float hh[TWO_D];
    int row = blockIdx.x;
    int b = row >> 8;
    int tid = threadIdx.x;   // 96
    float acc = 0.0f;
    if (tid < DD) v[tid] = x[row * DD + tid];
    for (int s = 0; s < SS; s++) {
        int j = ji[row * SS + s];
        int k = ki[row * SS + s];
        if (tid < DD) {
            v[DD + tid] = x[(b * NN + j) * DD + tid];
            v[2 * DD + tid] = x[(b * NN + k) * DD + tid];
        }
        __syncthreads();
        float h = B1[tid];
        #pragma unroll 8
        for (int c = 0; c < THREE_D; c++) h = fmaf(v[c], W1[c * TWO_D + tid], h);
        hh[tid] = gelu_exact(h);
        __syncthreads();
        if (tid < DD) {
            float p = B2[tid];
            #pragma unroll 8
            for (int k2 = 0; k2 < TWO_D; k2++) p = fmaf(hh[k2], W2[k2 * DD + tid], p);
            acc += p;
        }
    }
    if (tid < DD) outt[row * DD + tid] = acc * (1.0f / 6.0f);
}

// ---------------------------------------------------------------------------
// Gate + residual mix + LayerNorm 1. One block per row, 48 threads.
// ---------------------------------------------------------------------------
__global__ void mix_kernel(float* __restrict__ x,
                           const float* __restrict__ p,
                           const float* __restrict__ t,
                           const float* __restrict__ Gw,
                           const float* __restrict__ Gb,
                           const float* __restrict__ n1g,
                           const float* __restrict__ n1b) {
    __shared__ float sp[DD], st[DD], sy[DD];
    int row = blockIdx.x;
    int tid = threadIdx.x;  // 48
    sp[tid] = p[row * DD + tid];
    st[tid] = t[row * DD + tid];
    __syncthreads();
    float gsum = Gb[tid];
    #pragma unroll 8
    for (int c = 0; c < DD; c++) gsum = fmaf(sp[c], Gw[c * DD + tid], gsum);
    #pragma unroll 8
    for (int c = 0; c < DD; c++) gsum = fmaf(st[c], Gw[(DD + c) * DD + tid], gsum);
    float g = 1.0f / (1.0f + expf(-gsum));
    float y = x[row * DD + tid] + g * sp[tid] + (1.0f - g) * st[tid];
    sy[tid] = y;
    __syncthreads();
    float mu = 0.0f;
    #pragma unroll 8
    for (int c = 0; c < DD; c++) mu += sy[c];
    mu *= (1.0f / DD);
    float var = 0.0f;
    #pragma unroll 8
    for (int c = 0; c < DD; c++) { float d = sy[c] - mu; var = fmaf(d, d, var); }
    var *= (1.0f / DD);
    x[row * DD + tid] = (y - mu) * rsqrtf(var + 1e-5f) * n1g[tid] + n1b[tid];
}

// ---------------------------------------------------------------------------
// FFN + residual + LayerNorm 2. One block per row, 192 threads.
// ---------------------------------------------------------------------------
__global__ void ffn_kernel(float* __restrict__ x,
                           const float* __restrict__ W1,
                           const float* __restrict__ B1,
                           const float* __restrict__ W2,
                           const float* __restrict__ B2,
                           const float* __restrict__ n2g,
                           const float* __restrict__ n2b) {
    __shared__ float sx[DD], sh2[FOUR_D], sy[DD];
    int row = blockIdx.x;
    int tid = threadIdx.x;  // 192
    if (tid < DD) sx[tid] = x[row * DD + tid];
    __syncthreads();
    float h = B1[tid];
    #pragma unroll 8
    for (int c = 0; c < DD; c++) h = fmaf(sx[c], W1[c * FOUR_D + tid], h);
    sh2[tid] = gelu_exact(h);
    __syncthreads();
    if (tid < DD) {
        float o = B2[tid];
        #pragma unroll 8
        for (int k = 0; k < FOUR_D; k++) o = fmaf(sh2[k], W2[k * DD + tid], o);
        sy[tid] = sx[tid] + o;
    }
    __syncthreads();
    if (tid < DD) {
        float mu = 0.0f;
        #pragma unroll 8
        for (int c = 0; c < DD; c++) mu += sy[c];
        mu *= (1.0f / DD);
        float var = 0.0f;
        #pragma unroll 8
        for (int c = 0; c < DD; c++) { float d = sy[c] - mu; var = fmaf(d, d, var); }
        var *= (1.0f / DD);
        x[row * DD + tid] = (sy[tid] - mu) * rsqrtf(var + 1e-5f) * n2g[tid] + n2b[tid];
    }
}

// ---------------------------------------------------------------------------
// Head: out[b,n,:] = x @ head_w + head_b. One block per row, 32 threads.
// ---------------------------------------------------------------------------
__global__ void head_kernel(const float* __restrict__ x,
                            const float* __restrict__ Hw,
                            const float* __restrict__ Hb,
                            float* __restrict__ out) {
    __shared__ float sx[DD];
    int row = blockIdx.x;
    int tid = threadIdx.x;  // 32
    sx[tid] = x[row * DD + tid];
    if (tid < 16) sx[tid + 32] = x[row * DD + tid + 32];
    __syncwarp();
    if (tid < VV) {
        float o = Hb[tid];
        #pragma unroll 8
        for (int d = 0; d < DD; d++) o = fmaf(sx[d], Hw[d * VV + tid], o);
        out[row * VV + tid] = o;
    }
}

// ---------------------------------------------------------------------------
// Launch
// ---------------------------------------------------------------------------
extern "C" void kernel_launch(void* const* d_in, const int* in_sizes, int n_in,
                              void* d_out, int out_size) {
    const int*   ids     = (const int*)d_in[0];
    const int*   ji      = (const int*)d_in[1];
    const int*   ki      = (const int*)d_in[2];
    const float* embed   = (const float*)d_in[3];
    const float* pos     = (const float*)d_in[4];
    const float* pair_w1 = (const float*)d_in[5];
    const float* pair_b1 = (const float*)d_in[6];
    const float* pair_w2 = (const float*)d_in[7];
    const float* pair_b2 = (const float*)d_in[8];
    const float* tri_w1  = (const float*)d_in[9];
    const float* tri_b1  = (const float*)d_in[10];
    const float* tri_w2  = (const float*)d_in[11];
    const float* tri_b2  = (const float*)d_in[12];
    const float* gate_w  = (const float*)d_in[13];
    const float* gate_b  = (const float*)d_in[14];
    const float* n1_g    = (const float*)d_in[15];
    const float* n1_b    = (const float*)d_in[16];
    const float* ffn_w1  = (const float*)d_in[17];
    const float* ffn_b1  = (const float*)d_in[18];
    const float* ffn_w2  = (const float*)d_in[19];
    const float* ffn_b2  = (const float*)d_in[20];
    const float* n2_g    = (const float*)d_in[21];
    const float* n2_b    = (const float*)d_in[22];
    const float* head_w  = (const float*)d_in[23];
    const float* head_b  = (const float*)d_in[24];
    float* out = (float*)d_out;

    float* x; cudaGetSymbolAddress((void**)&x, g_x);
    float* p; cudaGetSymbolAddress((void**)&p, g_p);
    float* t; cudaGetSymbolAddress((void**)&t, g_t);

    static const int PAIR_SMEM =
        (TWO_D * TWO_D + TWO_D * DD + TWO_D + DD + DD +
         PAIR_WARPS * DD + PAIR_WARPS * TWO_D + PAIR_WARPS * 50) * (int)sizeof(float);
    cudaFuncSetAttribute(pair_kernel, cudaFuncAttributeMaxDynamicSharedMemorySize, PAIR_SMEM);

    embed_kernel<<<ROWS, DD>>>(ids, embed, pos, x);

    for (int l = 0; l < LL; l++) {
        pair_kernel<<<ROWS, PAIR_THREADS, PAIR_SMEM>>>(
            x,
            pair_w1 + l * TWO_D * TWO_D, pair_b1 + l * TWO_D,
            pair_w2 + l * TWO_D * DD,    pair_b2 + l * DD,
            p);
        triple_kernel<<<ROWS, TWO_D>>>(
            x,
            ji + l * ROWS * SS, ki + l * ROWS * SS,
            tri_w1 + l * THREE_D * TWO_D, tri_b1 + l * TWO_D,
            tri_w2 + l * TWO_D * DD,      tri_b2 + l * DD,
            t);
        mix_kernel<<<ROWS, DD>>>(
            x, p, t,
            gate_w + l * TWO_D * DD, gate_b + l * DD,
            n1_g + l * DD, n1_b + l * DD);
        ffn_kernel<<<ROWS, FOUR_D>>>(
            x,
            ffn_w1 + l * DD * FOUR_D, ffn_b1 + l * FOUR_D,
            ffn_w2 + l * FOUR_D * DD, ffn_b2 + l * DD,
            n2_g + l * DD, n2_b + l * DD);
    }

    head_kernel<<<ROWS, 32>>>(x, head_w, head_b, out);
}

// round 2
// speedup vs baseline: 4.6217x; 4.6217x over previous
#include <cuda_runtime.h>
#include <math.h>

#define BB 8
#define NN 256
#define DD 48
#define VV 20
#define LL 2
#define SS 6
#define TWO_D 96
#define THREE_D 144
#define FOUR_D 192
#define ROWS (BB*NN)   // 2048

// Scratch
__device__ float g_x[ROWS * DD];
__device__ float g_p[ROWS * DD];
__device__ float g_t[ROWS * DD];
__device__ float g_A[ROWS * TWO_D];   // xi @ W1_top + b1
__device__ float g_B[ROWS * TWO_D];   // xj @ W1_bot

__device__ __forceinline__ float gelu_exact(float v) {
    return 0.5f * v * (1.0f + erff(v * 0.70710678118654752440f));
}

// ---------------------------------------------------------------------------
// Embed
// ---------------------------------------------------------------------------
__global__ void embed_kernel(const int* __restrict__ ids,
                             const float* __restrict__ embed,
                             const float* __restrict__ pos,
                             float* __restrict__ x) {
    int row = blockIdx.x;
    int n = row & (NN - 1);
    int d = threadIdx.x;
    int id = ids[row];
    x[row * DD + d] = embed[id * DD + d] + pos[n * DD + d];
}

// ---------------------------------------------------------------------------
// Precompute A[row][96] = b1 + xi @ W1[0:48,:],  B[row][96] = xj @ W1[48:96,:]
// ---------------------------------------------------------------------------
__global__ __launch_bounds__(192) void ab_kernel(const float* __restrict__ x,
                          const float* __restrict__ W1,
                          const float* __restrict__ b1,
                          float* __restrict__ A,
                          float* __restrict__ Bv) {
    __shared__ float sx[8][DD];
    int r0 = blockIdx.x * 8;
    int tid = threadIdx.x;
    for (int idx = tid; idx < 8 * DD; idx += 192)
        sx[idx / DD][idx % DD] = x[(r0 + idx / DD) * DD + (idx % DD)];
    __syncthreads();
    int col = tid % TWO_D;
    int part = tid / TWO_D;   // 0 = A, 1 = B
    const float* w = W1 + (part ? DD * TWO_D : 0) + col;
    float acc[8];
    float init = part ? 0.0f : b1[col];
    #pragma unroll
    for (int r = 0; r < 8; r++) acc[r] = init;
    #pragma unroll 4
    for (int k = 0; k < DD; k++) {
        float wv = w[k * TWO_D];
        #pragma unroll
        for (int r = 0; r < 8; r++) acc[r] = fmaf(sx[r][k], wv, acc[r]);
    }
    float* dst = part ? Bv : A;
    #pragma unroll
    for (int r = 0; r < 8; r++) dst[(r0 + r) * TWO_D + col] = acc[r];
}

// ---------------------------------------------------------------------------
// Pair module: per (b,i), tiled GEMM over j with online softmax.
// ---------------------------------------------------------------------------
#define PJT 32
#define PTHREADS 128
#define HP 100   // row pitch (floats): 16B aligned, bank-conflict-free

__global__ __launch_bounds__(PTHREADS) void pair_kernel(
    const float* __restrict__ A, const float* __restrict__ Bv,
    const float* __restrict__ W2, const float* __restrict__ B2,
    float* __restrict__ outp) {
    __shared__ float sW2T[DD * HP];     // [d][k]
    __shared__ float sH[PJT * HP];      // [j][k]
    __shared__ float sA[TWO_D];
    __shared__ float sb2[DD];
    __shared__ float sw[PJT];
    __shared__ float sacc[8 * DD];
    __shared__ float slsum[8];

    int row = blockIdx.x;
    int b = row >> 8;
    int i = row & (NN - 1);
    int tid = threadIdx.x;
    int tx = tid & 15;
    int ty = tid >> 4;
    int d0 = tx * 3;

    for (int idx = tid; idx < TWO_D * DD; idx += PTHREADS) {
        int k = idx / DD, d = idx % DD;
        sW2T[d * HP + k] = W2[idx];
    }
    if (tid < TWO_D) sA[tid] = A[row * TWO_D + tid];
    if (tid < DD) sb2[tid] = B2[tid];
    __syncthreads();

    float M = -INFINITY;
    float acc0 = 0.0f, acc1 = 0.0f, acc2 = 0.0f;
    float lsum = 0.0f;
    int numJ = i + 1;
    const float* Bbase = Bv + (b * NN) * TWO_D;

    for (int jbase = 0; jbase < numJ; jbase += PJT) {
        // Build H tile: H[j][k] = gelu(A_i[k] + B_{jbase+j}[k])
        for (int q = tid; q < PJT * (TWO_D / 4); q += PTHREADS) {
            int j = q / (TWO_D / 4);
            int kk = (q % (TWO_D / 4)) * 4;
            float4 bv = *(const float4*)(Bbase + (jbase + j) * TWO_D + kk);
            float4 hv;
            hv.x = gelu_exact(sA[kk + 0] + bv.x);
            hv.y = gelu_exact(sA[kk + 1] + bv.y);
            hv.z = gelu_exact(sA[kk + 2] + bv.z);
            hv.w = gelu_exact(sA[kk + 3] + bv.w);
            *(float4*)(sH + j * HP + kk) = hv;
        }
        __syncthreads();

        // P tile = H @ W2 + b2 ; register tile 4j x 3d per thread
        float p[4][3];
        {
            float bb0 = sb2[d0], bb1 = sb2[d0 + 1], bb2v = sb2[d0 + 2];
            #pragma unroll
            for (int jj = 0; jj < 4; jj++) { p[jj][0] = bb0; p[jj][1] = bb1; p[jj][2] = bb2v; }
        }
        #pragma unroll 4
        for (int k = 0; k < TWO_D; k += 4) {
            float4 w0 = *(const float4*)(sW2T + (d0 + 0) * HP + k);
            float4 w1 = *(const float4*)(sW2T + (d0 + 1) * HP + k);
            float4 w2 = *(const float4*)(sW2T + (d0 + 2) * HP + k);
            #pragma unroll
            for (int jj = 0; jj < 4; jj++) {
                float4 h = *(const float4*)(sH + (ty + 8 * jj) * HP + k);
                p[jj][0] = fmaf(h.x, w0.x, p[jj][0]); p[jj][0] = fmaf(h.y, w0.y, p[jj][0]);
                p[jj][0] = fmaf(h.z, w0.z, p[jj][0]); p[jj][0] = fmaf(h.w, w0.w, p[jj][0]);
                p[jj][1] = fmaf(h.x, w1.x, p[jj][1]); p[jj][1] = fmaf(h.y, w1.y, p[jj][1]);
                p[jj][1] = fmaf(h.z, w1.z, p[jj][1]); p[jj][1] = fmaf(h.w, w1.w, p[jj][1]);
                p[jj][2] = fmaf(h.x, w2.x, p[jj][2]); p[jj][2] = fmaf(h.y, w2.y, p[jj][2]);
                p[jj][2] = fmaf(h.z, w2.z, p[jj][2]); p[jj][2] = fmaf(h.w, w2.w, p[jj][2]);
            }
        }

        // Pair-feature norms: reduce across the 16 tx lanes
        float wj[4];
        #pragma unroll
        for (int jj = 0; jj < 4; jj++) {
            float sq = p[jj][0] * p[jj][0] + p[jj][1] * p[jj][1] + p[jj][2] * p[jj][2];
            #pragma unroll
            for (int o = 1; o < 16; o <<= 1) sq += __shfl_xor_sync(0xFFFFFFFFu, sq, o);
            int j = jbase + ty + 8 * jj;
            wj[jj] = (j <= i) ? sqrtf(sq) : -INFINITY;
        }
        if (tx == 0) {
            #pragma unroll
            for (int jj = 0; jj < 4; jj++) sw[ty + 8 * jj] = wj[jj];
        }
        __syncthreads();

        // Block-consistent online softmax update
        float tmax = -INFINITY;
        #pragma unroll 8
        for (int q = 0; q < PJT; q++) tmax = fmaxf(tmax, sw[q]);
        float newM = fmaxf(M, tmax);
        float sc = (M == -INFINITY) ? 0.0f : expf(M - newM);
        acc0 *= sc; acc1 *= sc; acc2 *= sc; lsum *= sc;
        #pragma unroll
        for (int jj = 0; jj < 4; jj++) {
            float e = expf(wj[jj] - newM);   // exactly 0 for masked j
            acc0 = fmaf(e, p[jj][0], acc0);
            acc1 = fmaf(e, p[jj][1], acc1);
            acc2 = fmaf(e, p[jj][2], acc2);
            lsum += e;
        }
        M = newM;
        __syncthreads();   // protect sH / sw before next tile overwrites
    }

    sacc[ty * DD + d0 + 0] = acc0;
    sacc[ty * DD + d0 + 1] = acc1;
    sacc[ty * DD + d0 + 2] = acc2;
    if (tx == 0) slsum[ty] = lsum;
    __syncthreads();

    if (tid < DD) {
        float a = 0.0f, L = 0.0f;
        #pragma unroll
        for (int w = 0; w < 8; w++) { a += sacc[w * DD + tid]; L += slsum[w]; }
        outp[row * DD + tid] = a / L;
    }
}

// ---------------------------------------------------------------------------
// Triple module: gather all 6 (j,k) first, reuse each W1 load across s.
// ---------------------------------------------------------------------------
__global__ __launch_bounds__(TWO_D) void triple_kernel(const float* __restrict__ x,
                              const int* __restrict__ ji,
                              const int* __restrict__ ki,
                              const float* __restrict__ W1,
                              const float* __restrict__ B1,
                              const float* __restrict__ W2,
                              const float* __restrict__ B2,
                              float* __restrict__ outt) {
    __shared__ float v[SS][THREE_D];
    __shared__ float hh[SS][TWO_D];
    __shared__ int sidx[SS][2];
    int row = blockIdx.x;
    int b = row >> 8;
    int tid = threadIdx.x;
    if (tid < SS * 2) {
        int s = tid >> 1;
        sidx[s][tid & 1] = (tid & 1) ? ki[row * SS + s] : ji[row * SS + s];
    }
    __syncthreads();
    for (int idx = tid; idx < SS * THREE_D; idx += TWO_D) {
        int s = idx / THREE_D, c = idx % THREE_D;
        float val;
        if (c < DD)            val = x[row * DD + c];
        else if (c < 2 * DD)   val = x[(b * NN + sidx[s][0]) * DD + (c - DD)];
        else                   val = x[(b * NN + sidx[s][1]) * DD + (c - 2 * DD)];
        v[s][c] = val;
    }
    __syncthreads();
    {
        float h[SS];
        float bb = B1[tid];
        #pragma unroll
        for (int s = 0; s < SS; s++) h[s] = bb;
        #pragma unroll 4
        for (int k = 0; k < THREE_D; k++) {
            float w = W1[k * TWO_D + tid];
            #pragma unroll
            for (int s = 0; s < SS; s++) h[s] = fmaf(v[s][k], w, h[s]);
        }
        #pragma unroll
        for (int s = 0; s < SS; s++) hh[s][tid] = gelu_exact(h[s]);
    }
    __syncthreads();
    if (tid < DD) {
        float p[SS];
        float bb = B2[tid];
        #pragma unroll
        for (int s = 0; s < SS; s++) p[s] = bb;
        #pragma unroll 4
        for (int k = 0; k < TWO_D; k++) {
            float w = W2[k * DD + tid];
            #pragma unroll
            for (int s = 0; s < SS; s++) p[s] = fmaf(hh[s][k], w, p[s]);
        }
        float acc = 0.0f;
        #pragma unroll
        for (int s = 0; s < SS; s++) acc += p[s];
        outt[row * DD + tid] = acc * (1.0f / 6.0f);
    }
}

// ---------------------------------------------------------------------------
// Fused gate/mix/LN1 + FFN/LN2. 192 threads / block.
// ---------------------------------------------------------------------------
__global__ __launch_bounds__(FOUR_D) void mixffn_kernel(float* __restrict__ x,
                              const float* __restrict__ p,
                              const float* __restrict__ t,
                              const float* __restrict__ Gw,
                              const float* __restrict__ Gb,
                              const float* __restrict__ n1g,
                              const float* __restrict__ n1b,
                              const float* __restrict__ W1,
                              const float* __restrict__ B1,
                              const float* __restrict__ W2,
                              const float* __restrict__ B2,
                              const float* __restrict__ n2g,
                              const float* __restrict__ n2b) {
    __shared__ float sp[DD], st[DD], sx[DD], sy[DD], sg[2 * DD], sh2[FOUR_D];
    int row = blockIdx.x;
    int tid = threadIdx.x;
    if (tid < DD) {
        sp[tid] = p[row * DD + tid];
        st[tid] = t[row * DD + tid];
        sx[tid] = x[row * DD + tid];
    }
    __syncthreads();
    if (tid < 2 * DD) {
        int d = tid % DD;
        int part = tid / DD;
        const float* src = part ? st : sp;
        const float* gw = Gw + part * DD * DD;
        float s = 0.0f;
        #pragma unroll 8
        for (int c = 0; c < DD; c++) s = fmaf(src[c], gw[c * DD + d], s);
        sg[tid] = s;
    }
    __syncthreads();
    if (tid < DD) {
        float gsum = sg[tid] + sg[DD + tid] + Gb[tid];
        float g = 1.0f / (1.0f + expf(-gsum));
        sy[tid] = sx[tid] + g * sp[tid] + (1.0f - g) * st[tid];
    }
    __syncthreads();
    if (tid < DD) {
        float mu = 0.0f;
        #pragma unroll 8
        for (int c = 0; c < DD; c++) mu += sy[c];
        mu *= (1.0f / DD);
        float var = 0.0f;
        #pragma unroll 8
        for (int c = 0; c < DD; c++) { float d = sy[c] - mu; var = fmaf(d, d, var); }
        var *= (1.0f / DD);
        sp[tid] = (sy[tid] - mu) * rsqrtf(var + 1e-5f) * n1g[tid] + n1b[tid];
    }
    __syncthreads();
    {
        float h = B1[tid];
        #pragma unroll 8
        for (int c = 0; c < DD; c++) h = fmaf(sp[c], W1[c * FOUR_D + tid], h);
        sh2[tid] = gelu_exact(h);
    }
    __syncthreads();
    if (tid < DD) {
        float o = B2[tid];
        #pragma unroll 8
        for (int k = 0; k < FOUR_D; k++) o = fmaf(sh2[k], W2[k * DD + tid], o);
        sy[tid] = sp[tid] + o;
    }
    __syncthreads();
    if (tid < DD) {
        float mu = 0.0f;
        #pragma unroll 8
        for (int c = 0; c < DD; c++) mu += sy[c];
        mu *= (1.0f / DD);
        float var = 0.0f;
        #pragma unroll 8
        for (int c = 0; c < DD; c++) { float d = sy[c] - mu; var = fmaf(d, d, var); }
        var *= (1.0f / DD);
        x[row * DD + tid] = (sy[tid] - mu) * rsqrtf(var + 1e-5f) * n2g[tid] + n2b[tid];
    }
}

// ---------------------------------------------------------------------------
// Head
// ---------------------------------------------------------------------------
__global__ void head_kernel(const float* __restrict__ x,
                            const float* __restrict__ Hw,
                            const float* __restrict__ Hb,
                            float* __restrict__ out) {
    __shared__ float sx[DD];
    int row = blockIdx.x;
    int tid = threadIdx.x;
    sx[tid] = x[row * DD + tid];
    if (tid < 16) sx[tid + 32] = x[row * DD + tid + 32];
    __syncwarp();
    if (tid < VV) {
        float o = Hb[tid];
        #pragma unroll 8
        for (int d = 0; d < DD; d++) o = fmaf(sx[d], Hw[d * VV + tid], o);
        out[row * VV + tid] = o;
    }
}

// ---------------------------------------------------------------------------
// Launch
// ---------------------------------------------------------------------------
extern "C" void kernel_launch(void* const* d_in, const int* in_sizes, int n_in,
                              void* d_out, int out_size) {
    const int*   ids     = (const int*)d_in[0];
    const int*   ji      = (const int*)d_in[1];
    const int*   ki      = (const int*)d_in[2];
    const float* embed   = (const float*)d_in[3];
    const float* pos     = (const float*)d_in[4];
    const float* pair_w1 = (const float*)d_in[5];
    const float* pair_b1 = (const float*)d_in[6];
    const float* pair_w2 = (const float*)d_in[7];
    const float* pair_b2 = (const float*)d_in[8];
    const float* tri_w1  = (const float*)d_in[9];
    const float* tri_b1  = (const float*)d_in[10];
    const float* tri_w2  = (const float*)d_in[11];
    const float* tri_b2  = (const float*)d_in[12];
    const float* gate_w  = (const float*)d_in[13];
    const float* gate_b  = (const float*)d_in[14];
    const float* n1_g    = (const float*)d_in[15];
    const float* n1_b    = (const float*)d_in[16];
    const float* ffn_w1  = (const float*)d_in[17];
    const float* ffn_b1  = (const float*)d_in[18];
    const float* ffn_w2  = (const float*)d_in[19];
    const float* ffn_b2  = (const float*)d_in[20];
    const float* n2_g    = (const float*)d_in[21];
    const float* n2_b    = (const float*)d_in[22];
    const float* head_w  = (const float*)d_in[23];
    const float* head_b  = (const float*)d_in[24];
    float* out = (float*)d_out;

    float* x; cudaGetSymbolAddress((void**)&x, g_x);
    float* p; cudaGetSymbolAddress((void**)&p, g_p);
    float* t; cudaGetSymbolAddress((void**)&t, g_t);
    float* Aa; cudaGetSymbolAddress((void**)&Aa, g_A);
    float* Bb; cudaGetSymbolAddress((void**)&Bb, g_B);

    embed_kernel<<<ROWS, DD>>>(ids, embed, pos, x);

    for (int l = 0; l < LL; l++) {
        ab_kernel<<<ROWS / 8, 192>>>(x, pair_w1 + l * TWO_D * TWO_D,
                                     pair_b1 + l * TWO_D, Aa, Bb);
        pair_kernel<<<ROWS, PTHREADS>>>(Aa, Bb,
            pair_w2 + l * TWO_D * DD, pair_b2 + l * DD, p);
        triple_kernel<<<ROWS, TWO_D>>>(
            x, ji + l * ROWS * SS, ki + l * ROWS * SS,
            tri_w1 + l * THREE_D * TWO_D, tri_b1 + l * TWO_D,
            tri_w2 + l * TWO_D * DD,      tri_b2 + l * DD, t);
        mixffn_kernel<<<ROWS, FOUR_D>>>(
            x, p, t,
            gate_w + l * TWO_D * DD, gate_b + l * DD,
            n1_g + l * DD, n1_b + l * DD,
            ffn_w1 + l * DD * FOUR_D, ffn_b1 + l * FOUR_D,
            ffn_w2 + l * FOUR_D * DD, ffn_b2 + l * DD,
            n2_g + l * DD, n2_b + l * DD);
    }

    head_kernel<<<ROWS, 32>>>(x, head_w, head_b, out);
}